// round 15
// baseline (speedup 1.0000x reference)
#include <cuda_runtime.h>

typedef unsigned int u32;
typedef unsigned long long u64;

#define BB 8
#define NN 4096
#define KNB 20
#define TI 64
#define TJ 128
#define NEG_INF (-3.402823466e38f)
#define FULLM 0xFFFFFFFFu
// sentinel "worst" key: value-part 0x007FFFFF (= sort32(-inf) = ~sort32(+inf)), idx 0
#define SENT_LO ((u64)0x007FFFFFull << 32)

// ---------------- scratch (device globals; no allocations allowed) ----------
__device__ float d_g[NN * 64];              // mlp1(x[0])
__device__ float d_h[BB * NN * 64];         // stage-1 features
__device__ float d_hT2[BB * 32 * 65 * 128]; // tile-major hT + row64 = -|h|^2
__device__ float d_z[NN * 128];             // h[0] @ w4
__device__ float d_h2[BB * NN * 128];       // stage-2 features + b4

// ---------------- packed f32x2 + key helpers --------------------------------
__device__ __forceinline__ u64 ffma2(u64 a, u64 b, u64 c) {
    u64 d;
    asm("fma.rn.f32x2 %0, %1, %2, %3;" : "=l"(d) : "l"(a), "l"(b), "l"(c));
    return d;
}
__device__ __forceinline__ u64 add2(u64 a, u64 b) {
    u64 d;
    asm("add.rn.f32x2 %0, %1, %2;" : "=l"(d) : "l"(a), "l"(b));
    return d;
}
__device__ __forceinline__ u64 mul2(u64 a, u64 b) {
    u64 d;
    asm("mul.rn.f32x2 %0, %1, %2;" : "=l"(d) : "l"(a), "l"(b));
    return d;
}
__device__ __forceinline__ u64 pack2(float lo, float hi) {
    u64 r;
    asm("mov.b64 %0, {%1, %2};" : "=l"(r) : "f"(lo), "f"(hi));
    return r;
}
__device__ __forceinline__ void unpack2(u64 v, float& lo, float& hi) {
    asm("mov.b64 {%0, %1}, %2;" : "=f"(lo), "=f"(hi) : "l"(v));
}
// order-preserving float <-> uint bijection
__device__ __forceinline__ u32 sort32(float v) {
    u32 u = __float_as_uint(v);
    return u ^ ((u32)((int)u >> 31) | 0x80000000u);
}
__device__ __forceinline__ float unsort32(u32 s) {
    u32 u = (s & 0x80000000u) ? (s ^ 0x80000000u) : ~s;
    return __uint_as_float(u);
}
// shift-insert into distributed sorted top-20 (exact no-op if key <= list min)
__device__ __forceinline__ void sel_insert(u64& cur, u32 csv, int j) {
    u64 key = ((u64)csv << 32) | (u32)(4095 - j);
    u64 nxt = __shfl_down_sync(FULLM, cur, 1);
    u64 mx  = cur > key ? cur : key;
    cur = mx < nxt ? mx : nxt;
}

// ---------------- mbarrier / bulk-copy PTX -----------------------------------
#define MBAR_INIT(addr, cnt) \
    asm volatile("mbarrier.init.shared.b64 [%0], %1;" :: "r"(addr), "r"(cnt) : "memory")
#define MBAR_EXPECT_TX(addr, bytes) \
    asm volatile("mbarrier.arrive.expect_tx.shared.b64 _, [%0], %1;" :: "r"(addr), "r"(bytes) : "memory")
#define BULK_G2S(dst, src, bytes, mbar) \
    asm volatile("cp.async.bulk.shared::cluster.global.mbarrier::complete_tx::bytes [%0], [%1], %2, [%3];" \
                 :: "r"(dst), "l"(src), "r"(bytes), "r"(mbar) : "memory")
#define MBAR_WAIT(addr, parity) do {                                              \
    asm volatile(                                                                 \
        "{\n\t.reg .pred P;\n"                                                    \
        "W%=:\n\t"                                                                \
        "mbarrier.try_wait.parity.acquire.cta.shared::cta.b64 P, [%0], %1, 0x989680;\n\t" \
        "@P bra D%=;\n\t"                                                         \
        "bra W%=;\n"                                                              \
        "D%=:\n\t}"                                                               \
        :: "r"(addr), "r"(parity) : "memory");                                    \
} while (0)

// ---------------- K0: g = mlp1(x[0])  (3->64 relu ->64 relu ->64) -----------
__global__ __launch_bounds__(256) void k0_mlp_g(
    const float* __restrict__ x,
    const float* __restrict__ w1, const float* __restrict__ b1,
    const float* __restrict__ w2, const float* __restrict__ b2,
    const float* __restrict__ w3, const float* __restrict__ b3)
{
    __shared__ float sw1[3 * 64];
    __shared__ float sw2[64 * 64];
    __shared__ float sw3[64 * 64];
    __shared__ float sb1[64], sb2[64], sb3[64];
    __shared__ float sha[8][64];
    __shared__ float shb[8][64];
    int t = threadIdx.x;
    for (int i = t; i < 3 * 64; i += 256) sw1[i] = w1[i];
    for (int i = t; i < 64 * 64; i += 256) { sw2[i] = w2[i]; sw3[i] = w3[i]; }
    if (t < 64) { sb1[t] = b1[t]; sb2[t] = b2[t]; sb3[t] = b3[t]; }
    __syncthreads();

    int wid = t >> 5, lane = t & 31;
    int r = blockIdx.x * 8 + wid;
    float x0 = x[r * 3 + 0], x1 = x[r * 3 + 1], x2 = x[r * 3 + 2];
    int c0 = lane * 2;

    float a0 = fmaxf(fmaf(x2, sw1[128 + c0],     fmaf(x1, sw1[64 + c0],     fmaf(x0, sw1[c0],     sb1[c0]))),     0.f);
    float a1 = fmaxf(fmaf(x2, sw1[128 + c0 + 1], fmaf(x1, sw1[64 + c0 + 1], fmaf(x0, sw1[c0 + 1], sb1[c0 + 1]))), 0.f);
    sha[wid][c0] = a0; sha[wid][c0 + 1] = a1;
    __syncwarp();

    float u0 = sb2[c0], u1 = sb2[c0 + 1];
#pragma unroll
    for (int d = 0; d < 64; d++) {
        float hd = sha[wid][d];
        u0 = fmaf(hd, sw2[d * 64 + c0], u0);
        u1 = fmaf(hd, sw2[d * 64 + c0 + 1], u1);
    }
    u0 = fmaxf(u0, 0.f); u1 = fmaxf(u1, 0.f);
    shb[wid][c0] = u0; shb[wid][c0 + 1] = u1;
    __syncwarp();

    float v0 = sb3[c0], v1 = sb3[c0 + 1];
#pragma unroll
    for (int d = 0; d < 64; d++) {
        float hd = shb[wid][d];
        v0 = fmaf(hd, sw3[d * 64 + c0], v0);
        v1 = fmaf(hd, sw3[d * 64 + c0 + 1], v1);
    }
    d_g[r * 64 + c0] = v0;
    d_g[r * 64 + c0 + 1] = v1;
}

// ---------------- K1: knn1(xyz) + gather-max over g -> h, hT2 ---------------
// dyn smem (floats):
//   [0, 512)      sIu: 64 points x 4 u64 (x,y,z dup-packed; pad)
//   [512, 908)    sJn: 3 x 132 negated xj coords (coord-major)
//   [908, 2188)   sTop 64x20 (int)
//   [2188, 2444)  sSqP 64x4
#define K1_SMEM (2444 * 4)
__global__ __launch_bounds__(256, 4) void k1_knn1(const float* __restrict__ x)
{
    extern __shared__ float sm1[];
    u64*   sIu  = (u64*)sm1;
    float* sJn  = sm1 + 512;
    int*   sTop = (int*)(sm1 + 908);
    float* sSqP = sm1 + 2188;

    int t = threadIdx.x;
    int lane = t & 31;
    int w = t >> 5;
    int b = blockIdx.y;
    int i0 = blockIdx.x * TI;
    const float* xb = x + (size_t)b * NN * 3;

    for (int idx = t; idx < TI * 3; idx += 256) {
        int p = idx / 3, c = idx % 3;
        float v = xb[(i0 + p) * 3 + c];
        sIu[p * 4 + c] = pack2(v, v);
    }

    u64 lst[8];
#pragma unroll
    for (int p = 0; p < 8; p++) lst[p] = (lane < KNB) ? SENT_LO : ~0ull;

    for (int j0 = 0; j0 < NN; j0 += TJ) {
        __syncthreads();
        for (int idx = t; idx < TJ * 3; idx += 256) {
            int j = idx / 3, c = idx % 3;
            sJn[c * 132 + j] = -xb[(j0 + j) * 3 + c];
        }
        __syncthreads();

        ulonglong2 xj0 = *(const ulonglong2*)&sJn[0 * 132 + lane * 4];
        ulonglong2 xj1 = *(const ulonglong2*)&sJn[1 * 132 + lane * 4];
        ulonglong2 xj2 = *(const ulonglong2*)&sJn[2 * 132 + lane * 4];

#pragma unroll
        for (int p = 0; p < 8; p++) {
            u64 xi0 = sIu[(w * 8 + p) * 4 + 0];
            u64 xi1 = sIu[(w * 8 + p) * 4 + 1];
            u64 xi2 = sIu[(w * 8 + p) * 4 + 2];
            u64 e, a0, a1;
            e = add2(xi0, xj0.x); a0 = mul2(e, e);
            e = add2(xi1, xj1.x); a0 = ffma2(e, e, a0);
            e = add2(xi2, xj2.x); a0 = ffma2(e, e, a0);
            e = add2(xi0, xj0.y); a1 = mul2(e, e);
            e = add2(xi1, xj1.y); a1 = ffma2(e, e, a1);
            e = add2(xi2, xj2.y); a1 = ffma2(e, e, a1);
            float pf[4];
            unpack2(a0, pf[0], pf[1]); unpack2(a1, pf[2], pf[3]);

            u64 cur = lst[p];
            // smaller distance is better: pass if dist <= decoded 20th-best dist
            float thrF = unsort32(~(u32)(__shfl_sync(FULLM, cur, 0) >> 32));
#pragma unroll
            for (int s = 0; s < 4; s++) {
                u32 ball = __ballot_sync(FULLM, pf[s] <= thrF);
                while (ball) {
                    int src = __ffs(ball) - 1;
                    ball &= ball - 1;
                    float cp = __shfl_sync(FULLM, pf[s], src);
                    sel_insert(cur, ~sort32(cp), j0 + src * 4 + s);
                }
                thrF = unsort32(~(u32)(__shfl_sync(FULLM, cur, 0) >> 32));
            }
            lst[p] = cur;
        }
    }

    // write indices: lanes 0..19 hold the final top-20 per point
#pragma unroll
    for (int p = 0; p < 8; p++)
        if (lane < KNB)
            sTop[(w * 8 + p) * KNB + lane] = 4095 - (int)(lst[p] & 0xFFFu);
    __syncthreads();

    // gather-max over g: i = t>>2 (64 points), part = t&3 (16 channels each)
    int i = t >> 2, part = t & 3;
    float m[16];
#pragma unroll
    for (int c = 0; c < 16; c++) m[c] = NEG_INF;
    for (int k = 0; k < KNB; k++) {
        const float* gr = d_g + sTop[i * KNB + k] * 64 + part * 16;
#pragma unroll
        for (int c = 0; c < 16; c += 4) {
            float4 gv = *(const float4*)(gr + c);
            m[c]     = fmaxf(m[c],     gv.x);
            m[c + 1] = fmaxf(m[c + 1], gv.y);
            m[c + 2] = fmaxf(m[c + 2], gv.z);
            m[c + 3] = fmaxf(m[c + 3], gv.w);
        }
    }
    float sq = 0.f;
#pragma unroll
    for (int c = 0; c < 16; c++) sq = fmaf(m[c], m[c], sq);
    sSqP[i * 4 + part] = sq;

    int gi = i0 + i;
    float* hrow = d_h + ((size_t)b * NN + gi) * 64 + part * 16;
#pragma unroll
    for (int c = 0; c < 16; c += 4)
        *(float4*)(hrow + c) = make_float4(m[c], m[c + 1], m[c + 2], m[c + 3]);
    // tile-major transposed copy: d_hT2[b][jt][d][jc]
#pragma unroll
    for (int c = 0; c < 16; c++)
        d_hT2[(((size_t)b * 32 + (gi >> 7)) * 65 + part * 16 + c) * 128 + (gi & 127)] = m[c];
    __syncthreads();
    if (t < TI) {
        int gi2 = i0 + t;
        float s = sSqP[t * 4 + 0] + sSqP[t * 4 + 1] + sSqP[t * 4 + 2] + sSqP[t * 4 + 3];
        d_hT2[(((size_t)b * 32 + (gi2 >> 7)) * 65 + 64) * 128 + (gi2 & 127)] = -s;
    }
}

// ---------------- K2: z = h[0] @ w4  (4096x128, K=64) -----------------------
__global__ __launch_bounds__(256) void k2_z(const float* __restrict__ w4)
{
    __shared__ float sA[64 * 65];
    __shared__ float sB[64 * 128];
    int t = threadIdx.x;
    int m0 = blockIdx.x * 64;
    for (int idx = t; idx < 64 * 64; idx += 256) {
        int r = idx >> 6, d = idx & 63;
        sA[r * 65 + d] = d_h[(size_t)(m0 + r) * 64 + d];
    }
    for (int idx = t; idx < 64 * 128; idx += 256) sB[idx] = w4[idx];
    __syncthreads();

    int tx = t & 15, ty = t >> 4;
    float acc[4][8];
#pragma unroll
    for (int ii = 0; ii < 4; ii++)
#pragma unroll
        for (int jj = 0; jj < 8; jj++) acc[ii][jj] = 0.f;

#pragma unroll 8
    for (int d = 0; d < 64; d++) {
        float a[4];
#pragma unroll
        for (int ii = 0; ii < 4; ii++) a[ii] = sA[(ty * 4 + ii) * 65 + d];
        float4 q0 = *(float4*)&sB[d * 128 + tx * 8];
        float4 q1 = *(float4*)&sB[d * 128 + tx * 8 + 4];
        float bb[8] = {q0.x, q0.y, q0.z, q0.w, q1.x, q1.y, q1.z, q1.w};
#pragma unroll
        for (int ii = 0; ii < 4; ii++)
#pragma unroll
            for (int jj = 0; jj < 8; jj++) acc[ii][jj] = fmaf(a[ii], bb[jj], acc[ii][jj]);
    }
#pragma unroll
    for (int ii = 0; ii < 4; ii++) {
        float* zr = d_z + (size_t)(m0 + ty * 4 + ii) * 128 + tx * 8;
        *(float4*)(zr)     = make_float4(acc[ii][0], acc[ii][1], acc[ii][2], acc[ii][3]);
        *(float4*)(zr + 4) = make_float4(acc[ii][4], acc[ii][5], acc[ii][6], acc[ii][7]);
    }
}

// ---------------- K3: knn2(64-d) + gather-max over z + b4 -> h2 -------------
// 128 threads, 4 warps x 16 points/warp (halves B-read phases per unit work).
// dyn smem (floats):
//   [0, 8320)        sJ buf0: 65 x 128 (row 64 = -|h|^2)
//   [8320, 16640)    sJ buf1
//   [16640, 20736)   sIf: 64 points x 64 floats (h, plain)
//   [20736, 22016)   sTop 64x20 (int)
//   [22016, 22020)   mbar[2] (u64 x2)
#define K3_TILE_BYTES (65 * 128 * 4)
#define K3_SMEM (22024 * 4)
__global__ __launch_bounds__(128, 2) void k3_knn2(const float* __restrict__ b4)
{
    extern __shared__ float sm3[];
    float* sJ0  = sm3;
    float* sJ1  = sm3 + 8320;
    float* sIf  = sm3 + 16640;
    int*   sTop = (int*)(sm3 + 20736);

    int t = threadIdx.x;
    int lane = t & 31;
    int w = t >> 5;                 // 0..3, warp owns points w*16..w*16+15
    int b = blockIdx.y;
    int i0 = blockIdx.x * TI;

    u32 sbase = (u32)__cvta_generic_to_shared(sm3);
    u32 mb0 = sbase + 22016 * 4;
    u32 mb1 = mb0 + 8;
    const float* src_base = d_hT2 + (size_t)b * 32 * 8320;

    // fill sIf: 64 points x 64 dims (plain float4 copy)
    {
        const float4* src = (const float4*)d_h;
        for (int idx = t; idx < 64 * 16; idx += 128) {
            int r = idx >> 4, c4 = idx & 15;
            *(float4*)&sIf[r * 64 + c4 * 4] = src[((size_t)b * NN + i0 + r) * 16 + c4];
        }
    }
    if (t == 0) { MBAR_INIT(mb0, 1); MBAR_INIT(mb1, 1); }
    __syncthreads();
    if (t == 0) {
        MBAR_EXPECT_TX(mb0, K3_TILE_BYTES);
        BULK_G2S(sbase, src_base, K3_TILE_BYTES, mb0);
    }

    u64 lst[16];
#pragma unroll
    for (int p = 0; p < 16; p++) lst[p] = (lane < KNB) ? SENT_LO : ~0ull;

    const u64 TWO2 = pack2(2.f, 2.f);

    for (int tt = 0; tt < 32; tt++) {
        __syncthreads();                      // everyone done with buf[(tt+1)&1]
        if (t == 0 && tt + 1 < 32) {
            u32 mbn = ((tt + 1) & 1) ? mb1 : mb0;
            u32 dstn = sbase + (((tt + 1) & 1) ? 8320 * 4 : 0);
            MBAR_EXPECT_TX(mbn, K3_TILE_BYTES);
            BULK_G2S(dstn, src_base + (size_t)(tt + 1) * 8320, K3_TILE_BYTES, mbn);
        }
        u32 mbc = (tt & 1) ? mb1 : mb0;
        MBAR_WAIT(mbc, (tt >> 1) & 1);
        const float* buf = (tt & 1) ? sJ1 : sJ0;
        int j0 = tt * TJ;

        u64 acc[16][2];
#pragma unroll
        for (int p = 0; p < 16; p++) { acc[p][0] = 0ull; acc[p][1] = 0ull; }

#pragma unroll 2
        for (int d4 = 0; d4 < 16; d4++) {
            ulonglong2 bb[4];
#pragma unroll
            for (int dd = 0; dd < 4; dd++)
                bb[dd] = *(const ulonglong2*)&buf[(d4 * 4 + dd) * 128 + lane * 4];
#pragma unroll
            for (int p = 0; p < 16; p++) {
                float4 af = *(const float4*)&sIf[(w * 16 + p) * 64 + d4 * 4];
                u64 a0 = pack2(af.x, af.x);
                u64 a1 = pack2(af.y, af.y);
                u64 a2 = pack2(af.z, af.z);
                u64 a3 = pack2(af.w, af.w);
                acc[p][0] = ffma2(a0, bb[0].x, acc[p][0]);
                acc[p][1] = ffma2(a0, bb[0].y, acc[p][1]);
                acc[p][0] = ffma2(a1, bb[1].x, acc[p][0]);
                acc[p][1] = ffma2(a1, bb[1].y, acc[p][1]);
                acc[p][0] = ffma2(a2, bb[2].x, acc[p][0]);
                acc[p][1] = ffma2(a2, bb[2].y, acc[p][1]);
                acc[p][0] = ffma2(a3, bb[3].x, acc[p][0]);
                acc[p][1] = ffma2(a3, bb[3].y, acc[p][1]);
            }
        }

        ulonglong2 nq = *(const ulonglong2*)&buf[64 * 128 + lane * 4];
#pragma unroll
        for (int p = 0; p < 16; p++) {
            u64 pd0 = ffma2(acc[p][0], TWO2, nq.x);
            u64 pd1 = ffma2(acc[p][1], TWO2, nq.y);
            float pf[4];
            unpack2(pd0, pf[0], pf[1]); unpack2(pd1, pf[2], pf[3]);

            u64 cur = lst[p];
            float thrF = unsort32((u32)(__shfl_sync(FULLM, cur, 0) >> 32));
#pragma unroll
            for (int s = 0; s < 4; s++) {
                u32 ball = __ballot_sync(FULLM, pf[s] >= thrF);
                while (ball) {
                    int src = __ffs(ball) - 1;
                    ball &= ball - 1;
                    float cp = __shfl_sync(FULLM, pf[s], src);
                    sel_insert(cur, sort32(cp), j0 + src * 4 + s);
                }
                thrF = unsort32((u32)(__shfl_sync(FULLM, cur, 0) >> 32));
            }
            lst[p] = cur;
        }
    }

#pragma unroll
    for (int p = 0; p < 16; p++)
        if (lane < KNB)
            sTop[(w * 16 + p) * KNB + lane] = 4095 - (int)(lst[p] & 0xFFFu);
    __syncthreads();

    // gather-max over z: i = t>>1 (64 points), part = t&1 (64 channels each, 2 halves)
    int i = t >> 1, part = t & 1;
    int gi = i0 + i;
#pragma unroll
    for (int half = 0; half < 2; half++) {
        int cbase = part * 64 + half * 32;
        float m[32];
#pragma unroll
        for (int c = 0; c < 32; c++) m[c] = NEG_INF;
        for (int k = 0; k < KNB; k++) {
            const float* zr = d_z + sTop[i * KNB + k] * 128 + cbase;
#pragma unroll
            for (int c = 0; c < 32; c += 4) {
                float4 zv = *(const float4*)(zr + c);
                m[c]     = fmaxf(m[c],     zv.x);
                m[c + 1] = fmaxf(m[c + 1], zv.y);
                m[c + 2] = fmaxf(m[c + 2], zv.z);
                m[c + 3] = fmaxf(m[c + 3], zv.w);
            }
        }
        float* orow = d_h2 + ((size_t)b * NN + gi) * 128 + cbase;
        const float* b4p = b4 + cbase;
#pragma unroll
        for (int c = 0; c < 32; c += 4) {
            *(float4*)(orow + c) = make_float4(m[c] + b4p[c], m[c + 1] + b4p[c + 1],
                                               m[c + 2] + b4p[c + 2], m[c + 3] + b4p[c + 3]);
        }
    }
}

// ---------------- K4: out = h2 @ w5 + b5  (32768x1024, K=128) ---------------
// 128 threads, 8x8 per-thread tile (1.0 B/MAC LDS).
// dyn smem (floats): sA 64x132 [0,8448), sB 128x128 [8448,24832), bias [24832,24960)
#define K4_SMEM (24960 * 4)
__global__ __launch_bounds__(128, 2) void k4_out(
    const float* __restrict__ w5, const float* __restrict__ b5, float* __restrict__ out)
{
    extern __shared__ float sm4[];
    float* sA    = sm4;
    float* sB    = sm4 + 8448;
    float* sBias = sm4 + 24832;

    int t = threadIdx.x;
    int m0 = blockIdx.x * 64;
    int c0 = blockIdx.y * 128;

    {
        const float4* src = (const float4*)d_h2;
        for (int idx = t; idx < 64 * 32; idx += 128) {
            int r = idx >> 5, c4 = idx & 31;
            *(float4*)&sA[r * 132 + c4 * 4] = src[((size_t)m0 + r) * 32 + c4];
        }
    }
    for (int idx = t; idx < 128 * 32; idx += 128) {
        int d = idx >> 5, c4 = idx & 31;
        *(float4*)&sB[d * 128 + c4 * 4] = *(const float4*)&w5[(size_t)d * 1024 + c0 + c4 * 4];
    }
    sBias[t] = b5[c0 + t];
    __syncthreads();

    int tx = t & 15, ty = t >> 4;          // ty 0..7 -> rows ty*8..ty*8+7
    u64 acc[8][4];
#pragma unroll
    for (int ii = 0; ii < 8; ii++)
#pragma unroll
        for (int pp = 0; pp < 4; pp++) acc[ii][pp] = 0ull;

#pragma unroll 2
    for (int d4 = 0; d4 < 32; d4++) {
        float af[8][4];
#pragma unroll
        for (int ii = 0; ii < 8; ii++)
            *(float4*)af[ii] = *(float4*)&sA[(ty * 8 + ii) * 132 + d4 * 4];
#pragma unroll
        for (int dd = 0; dd < 4; dd++) {
            const ulonglong2* bp = (const ulonglong2*)&sB[(d4 * 4 + dd) * 128 + tx * 8];
            ulonglong2 b0 = bp[0];
            ulonglong2 b1 = bp[1];
#pragma unroll
            for (int ii = 0; ii < 8; ii++) {
                u64 a2 = pack2(af[ii][dd], af[ii][dd]);
                acc[ii][0] = ffma2(a2, b0.x, acc[ii][0]);
                acc[ii][1] = ffma2(a2, b0.y, acc[ii][1]);
                acc[ii][2] = ffma2(a2, b1.x, acc[ii][2]);
                acc[ii][3] = ffma2(a2, b1.y, acc[ii][3]);
            }
        }
    }

    const ulonglong2* bi = (const ulonglong2*)&sBias[tx * 8];
    ulonglong2 bv0 = bi[0], bv1 = bi[1];
    const u64 ONE2 = pack2(1.f, 1.f);
#pragma unroll
    for (int ii = 0; ii < 8; ii++) {
        ulonglong2 r0, r1;
        r0.x = ffma2(acc[ii][0], ONE2, bv0.x);
        r0.y = ffma2(acc[ii][1], ONE2, bv0.y);
        r1.x = ffma2(acc[ii][2], ONE2, bv1.x);
        r1.y = ffma2(acc[ii][3], ONE2, bv1.y);
        size_t row = (size_t)(m0 + ty * 8 + ii) * 1024 + c0 + tx * 8;
        *(ulonglong2*)&out[row]     = r0;
        *(ulonglong2*)&out[row + 4] = r1;
    }
}

// ---------------- launch -----------------------------------------------------
extern "C" void kernel_launch(void* const* d_in, const int* in_sizes, int n_in,
                              void* d_out, int out_size)
{
    const float* x  = (const float*)d_in[0];
    const float* w1 = (const float*)d_in[1];
    const float* b1 = (const float*)d_in[2];
    const float* w2 = (const float*)d_in[3];
    const float* b2 = (const float*)d_in[4];
    const float* w3 = (const float*)d_in[5];
    const float* b3 = (const float*)d_in[6];
    const float* w4 = (const float*)d_in[7];
    const float* b4 = (const float*)d_in[8];
    const float* w5 = (const float*)d_in[9];
    const float* b5 = (const float*)d_in[10];
    float* out = (float*)d_out;

    cudaFuncSetAttribute(k1_knn1, cudaFuncAttributeMaxDynamicSharedMemorySize, K1_SMEM);
    cudaFuncSetAttribute(k3_knn2, cudaFuncAttributeMaxDynamicSharedMemorySize, K3_SMEM);
    cudaFuncSetAttribute(k4_out,  cudaFuncAttributeMaxDynamicSharedMemorySize, K4_SMEM);

    k0_mlp_g<<<NN / 8, 256>>>(x, w1, b1, w2, b2, w3, b3);
    k1_knn1<<<dim3(NN / TI, BB), 256, K1_SMEM>>>(x);
    k2_z<<<NN / 64, 256>>>(w4);
    k3_knn2<<<dim3(NN / TI, BB), 128, K3_SMEM>>>(b4);
    k4_out<<<dim3((BB * NN) / 64, 1024 / 128), 128, K4_SMEM>>>(w5, b5, out);
}

// round 16
// speedup vs baseline: 1.1196x; 1.1196x over previous
#include <cuda_runtime.h>

typedef unsigned int u32;
typedef unsigned long long u64;

#define BB 8
#define NN 4096
#define KNB 20
#define TI 64
#define TJ 128
#define NEG_INF (-3.402823466e38f)
#define FULLM 0xFFFFFFFFu
// sentinel "worst" key: value-part 0x007FFFFF (= sort32(-inf) = ~sort32(+inf)), idx 0
#define SENT_LO ((u64)0x007FFFFFull << 32)

// ---------------- scratch (device globals; no allocations allowed) ----------
__device__ float d_g[NN * 64];              // mlp1(x[0])
__device__ float d_h[BB * NN * 64];         // stage-1 features
__device__ float d_hT2[BB * 32 * 65 * 128]; // tile-major hT + row64 = -|h|^2
__device__ float d_z[NN * 128];             // h[0] @ w4
__device__ float d_h2[BB * NN * 128];       // stage-2 features + b4

// ---------------- packed f32x2 + key helpers --------------------------------
__device__ __forceinline__ u64 ffma2(u64 a, u64 b, u64 c) {
    u64 d;
    asm("fma.rn.f32x2 %0, %1, %2, %3;" : "=l"(d) : "l"(a), "l"(b), "l"(c));
    return d;
}
__device__ __forceinline__ u64 add2(u64 a, u64 b) {
    u64 d;
    asm("add.rn.f32x2 %0, %1, %2;" : "=l"(d) : "l"(a), "l"(b));
    return d;
}
__device__ __forceinline__ u64 mul2(u64 a, u64 b) {
    u64 d;
    asm("mul.rn.f32x2 %0, %1, %2;" : "=l"(d) : "l"(a), "l"(b));
    return d;
}
__device__ __forceinline__ u64 pack2(float lo, float hi) {
    u64 r;
    asm("mov.b64 %0, {%1, %2};" : "=l"(r) : "f"(lo), "f"(hi));
    return r;
}
__device__ __forceinline__ void unpack2(u64 v, float& lo, float& hi) {
    asm("mov.b64 {%0, %1}, %2;" : "=f"(lo), "=f"(hi) : "l"(v));
}
// order-preserving float <-> uint bijection
__device__ __forceinline__ u32 sort32(float v) {
    u32 u = __float_as_uint(v);
    return u ^ ((u32)((int)u >> 31) | 0x80000000u);
}
__device__ __forceinline__ float unsort32(u32 s) {
    u32 u = (s & 0x80000000u) ? (s ^ 0x80000000u) : ~s;
    return __uint_as_float(u);
}
// shift-insert into distributed sorted top-20 (exact no-op if key <= list min)
__device__ __forceinline__ void sel_insert(u64& cur, u32 csv, int j) {
    u64 key = ((u64)csv << 32) | (u32)(4095 - j);
    u64 nxt = __shfl_down_sync(FULLM, cur, 1);
    u64 mx  = cur > key ? cur : key;
    cur = mx < nxt ? mx : nxt;
}

// ---------------- mbarrier / bulk-copy PTX -----------------------------------
#define MBAR_INIT(addr, cnt) \
    asm volatile("mbarrier.init.shared.b64 [%0], %1;" :: "r"(addr), "r"(cnt) : "memory")
#define MBAR_EXPECT_TX(addr, bytes) \
    asm volatile("mbarrier.arrive.expect_tx.shared.b64 _, [%0], %1;" :: "r"(addr), "r"(bytes) : "memory")
#define BULK_G2S(dst, src, bytes, mbar) \
    asm volatile("cp.async.bulk.shared::cluster.global.mbarrier::complete_tx::bytes [%0], [%1], %2, [%3];" \
                 :: "r"(dst), "l"(src), "r"(bytes), "r"(mbar) : "memory")
#define MBAR_WAIT(addr, parity) do {                                              \
    asm volatile(                                                                 \
        "{\n\t.reg .pred P;\n"                                                    \
        "W%=:\n\t"                                                                \
        "mbarrier.try_wait.parity.acquire.cta.shared::cta.b64 P, [%0], %1, 0x989680;\n\t" \
        "@P bra D%=;\n\t"                                                         \
        "bra W%=;\n"                                                              \
        "D%=:\n\t}"                                                               \
        :: "r"(addr), "r"(parity) : "memory");                                    \
} while (0)

// ---------------- K0: g = mlp1(x[0])  (3->64 relu ->64 relu ->64) -----------
__global__ __launch_bounds__(256) void k0_mlp_g(
    const float* __restrict__ x,
    const float* __restrict__ w1, const float* __restrict__ b1,
    const float* __restrict__ w2, const float* __restrict__ b2,
    const float* __restrict__ w3, const float* __restrict__ b3)
{
    __shared__ float sw1[3 * 64];
    __shared__ float sw2[64 * 64];
    __shared__ float sw3[64 * 64];
    __shared__ float sb1[64], sb2[64], sb3[64];
    __shared__ float sha[8][64];
    __shared__ float shb[8][64];
    int t = threadIdx.x;
    for (int i = t; i < 3 * 64; i += 256) sw1[i] = w1[i];
    for (int i = t; i < 64 * 64; i += 256) { sw2[i] = w2[i]; sw3[i] = w3[i]; }
    if (t < 64) { sb1[t] = b1[t]; sb2[t] = b2[t]; sb3[t] = b3[t]; }
    __syncthreads();

    int wid = t >> 5, lane = t & 31;
    int r = blockIdx.x * 8 + wid;
    float x0 = x[r * 3 + 0], x1 = x[r * 3 + 1], x2 = x[r * 3 + 2];
    int c0 = lane * 2;

    float a0 = fmaxf(fmaf(x2, sw1[128 + c0],     fmaf(x1, sw1[64 + c0],     fmaf(x0, sw1[c0],     sb1[c0]))),     0.f);
    float a1 = fmaxf(fmaf(x2, sw1[128 + c0 + 1], fmaf(x1, sw1[64 + c0 + 1], fmaf(x0, sw1[c0 + 1], sb1[c0 + 1]))), 0.f);
    sha[wid][c0] = a0; sha[wid][c0 + 1] = a1;
    __syncwarp();

    float u0 = sb2[c0], u1 = sb2[c0 + 1];
#pragma unroll
    for (int d = 0; d < 64; d++) {
        float hd = sha[wid][d];
        u0 = fmaf(hd, sw2[d * 64 + c0], u0);
        u1 = fmaf(hd, sw2[d * 64 + c0 + 1], u1);
    }
    u0 = fmaxf(u0, 0.f); u1 = fmaxf(u1, 0.f);
    shb[wid][c0] = u0; shb[wid][c0 + 1] = u1;
    __syncwarp();

    float v0 = sb3[c0], v1 = sb3[c0 + 1];
#pragma unroll
    for (int d = 0; d < 64; d++) {
        float hd = shb[wid][d];
        v0 = fmaf(hd, sw3[d * 64 + c0], v0);
        v1 = fmaf(hd, sw3[d * 64 + c0 + 1], v1);
    }
    d_g[r * 64 + c0] = v0;
    d_g[r * 64 + c0 + 1] = v1;
}

// ---------------- K1: knn1(xyz) + gather-max over g -> h, hT2 ---------------
// j-tiles read directly from gmem (L2-hot): 3 LDG.128 per lane per tile.
// dyn smem (floats):
//   [0, 512)      sIu: 64 points x 4 u64 (x,y,z dup-packed; pad)
//   [512, 1792)   sTop 64x20 (int)
//   [1792, 2048)  sSqP 64x4
#define K1_SMEM (2048 * 4)
__global__ __launch_bounds__(256, 4) void k1_knn1(const float* __restrict__ x)
{
    extern __shared__ float sm1[];
    u64*   sIu  = (u64*)sm1;
    int*   sTop = (int*)(sm1 + 512);
    float* sSqP = sm1 + 1792;

    int t = threadIdx.x;
    int lane = t & 31;
    int w = t >> 5;
    int b = blockIdx.y;
    int i0 = blockIdx.x * TI;
    const float* xb = x + (size_t)b * NN * 3;
    const float4* xb4 = (const float4*)xb;

    for (int idx = t; idx < TI * 3; idx += 256) {
        int p = idx / 3, c = idx % 3;
        float v = xb[(i0 + p) * 3 + c];
        sIu[p * 4 + c] = pack2(v, v);
    }

    u64 lst[8];
#pragma unroll
    for (int p = 0; p < 8; p++) lst[p] = (lane < KNB) ? SENT_LO : ~0ull;

    __syncthreads();   // sIu visible; main loop below is barrier-free

    for (int j0 = 0; j0 < NN; j0 += TJ) {
        // lane's 4 j-points: 12 consecutive floats = 3 float4 (alignment: (j0+lane*4)*3 % 4 == 0)
        int fb = ((j0 >> 2) + lane) * 3;
        float4 q0 = xb4[fb + 0];   // x0 y0 z0 x1
        float4 q1 = xb4[fb + 1];   // y1 z1 x2 y2
        float4 q2 = xb4[fb + 2];   // z2 x3 y3 z3
        ulonglong2 xj0, xj1, xj2;
        xj0.x = pack2(-q0.x, -q0.w); xj0.y = pack2(-q1.z, -q2.y);   // -x pairs
        xj1.x = pack2(-q0.y, -q1.x); xj1.y = pack2(-q1.w, -q2.z);   // -y pairs
        xj2.x = pack2(-q0.z, -q1.y); xj2.y = pack2(-q2.x, -q2.w);   // -z pairs

#pragma unroll
        for (int p = 0; p < 8; p++) {
            u64 xi0 = sIu[(w * 8 + p) * 4 + 0];
            u64 xi1 = sIu[(w * 8 + p) * 4 + 1];
            u64 xi2 = sIu[(w * 8 + p) * 4 + 2];
            u64 e, a0, a1;
            e = add2(xi0, xj0.x); a0 = mul2(e, e);
            e = add2(xi1, xj1.x); a0 = ffma2(e, e, a0);
            e = add2(xi2, xj2.x); a0 = ffma2(e, e, a0);
            e = add2(xi0, xj0.y); a1 = mul2(e, e);
            e = add2(xi1, xj1.y); a1 = ffma2(e, e, a1);
            e = add2(xi2, xj2.y); a1 = ffma2(e, e, a1);
            float pf[4];
            unpack2(a0, pf[0], pf[1]); unpack2(a1, pf[2], pf[3]);

            u64 cur = lst[p];
            // smaller distance is better: pass if dist <= decoded 20th-best dist
            float thrF = unsort32(~(u32)(__shfl_sync(FULLM, cur, 0) >> 32));
#pragma unroll
            for (int s = 0; s < 4; s++) {
                // candidate order within lane: s=0 -> j0+lane*4+0, ..., s=3 -> +3
                u32 ball = __ballot_sync(FULLM, pf[s] <= thrF);
                while (ball) {
                    int src = __ffs(ball) - 1;
                    ball &= ball - 1;
                    float cp = __shfl_sync(FULLM, pf[s], src);
                    sel_insert(cur, ~sort32(cp), j0 + src * 4 + s);
                }
                thrF = unsort32(~(u32)(__shfl_sync(FULLM, cur, 0) >> 32));
            }
            lst[p] = cur;
        }
    }

    // write indices: lanes 0..19 hold the final top-20 per point
#pragma unroll
    for (int p = 0; p < 8; p++)
        if (lane < KNB)
            sTop[(w * 8 + p) * KNB + lane] = 4095 - (int)(lst[p] & 0xFFFu);
    __syncthreads();

    // gather-max over g: i = t>>2 (64 points), part = t&3 (16 channels each)
    int i = t >> 2, part = t & 3;
    float m[16];
#pragma unroll
    for (int c = 0; c < 16; c++) m[c] = NEG_INF;
    for (int k = 0; k < KNB; k++) {
        const float* gr = d_g + sTop[i * KNB + k] * 64 + part * 16;
#pragma unroll
        for (int c = 0; c < 16; c += 4) {
            float4 gv = *(const float4*)(gr + c);
            m[c]     = fmaxf(m[c],     gv.x);
            m[c + 1] = fmaxf(m[c + 1], gv.y);
            m[c + 2] = fmaxf(m[c + 2], gv.z);
            m[c + 3] = fmaxf(m[c + 3], gv.w);
        }
    }
    float sq = 0.f;
#pragma unroll
    for (int c = 0; c < 16; c++) sq = fmaf(m[c], m[c], sq);
    sSqP[i * 4 + part] = sq;

    int gi = i0 + i;
    float* hrow = d_h + ((size_t)b * NN + gi) * 64 + part * 16;
#pragma unroll
    for (int c = 0; c < 16; c += 4)
        *(float4*)(hrow + c) = make_float4(m[c], m[c + 1], m[c + 2], m[c + 3]);
    // tile-major transposed copy: d_hT2[b][jt][d][jc]
#pragma unroll
    for (int c = 0; c < 16; c++)
        d_hT2[(((size_t)b * 32 + (gi >> 7)) * 65 + part * 16 + c) * 128 + (gi & 127)] = m[c];
    __syncthreads();
    if (t < TI) {
        int gi2 = i0 + t;
        float s = sSqP[t * 4 + 0] + sSqP[t * 4 + 1] + sSqP[t * 4 + 2] + sSqP[t * 4 + 3];
        d_hT2[(((size_t)b * 32 + (gi2 >> 7)) * 65 + 64) * 128 + (gi2 & 127)] = -s;
    }
}

// ---------------- K2: z = h[0] @ w4  (4096x128, K=64) -----------------------
__global__ __launch_bounds__(256) void k2_z(const float* __restrict__ w4)
{
    __shared__ float sA[64 * 65];
    __shared__ float sB[64 * 128];
    int t = threadIdx.x;
    int m0 = blockIdx.x * 64;
    for (int idx = t; idx < 64 * 64; idx += 256) {
        int r = idx >> 6, d = idx & 63;
        sA[r * 65 + d] = d_h[(size_t)(m0 + r) * 64 + d];
    }
    for (int idx = t; idx < 64 * 128; idx += 256) sB[idx] = w4[idx];
    __syncthreads();

    int tx = t & 15, ty = t >> 4;
    float acc[4][8];
#pragma unroll
    for (int ii = 0; ii < 4; ii++)
#pragma unroll
        for (int jj = 0; jj < 8; jj++) acc[ii][jj] = 0.f;

#pragma unroll 8
    for (int d = 0; d < 64; d++) {
        float a[4];
#pragma unroll
        for (int ii = 0; ii < 4; ii++) a[ii] = sA[(ty * 4 + ii) * 65 + d];
        float4 q0 = *(float4*)&sB[d * 128 + tx * 8];
        float4 q1 = *(float4*)&sB[d * 128 + tx * 8 + 4];
        float bb[8] = {q0.x, q0.y, q0.z, q0.w, q1.x, q1.y, q1.z, q1.w};
#pragma unroll
        for (int ii = 0; ii < 4; ii++)
#pragma unroll
            for (int jj = 0; jj < 8; jj++) acc[ii][jj] = fmaf(a[ii], bb[jj], acc[ii][jj]);
    }
#pragma unroll
    for (int ii = 0; ii < 4; ii++) {
        float* zr = d_z + (size_t)(m0 + ty * 4 + ii) * 128 + tx * 8;
        *(float4*)(zr)     = make_float4(acc[ii][0], acc[ii][1], acc[ii][2], acc[ii][3]);
        *(float4*)(zr + 4) = make_float4(acc[ii][4], acc[ii][5], acc[ii][6], acc[ii][7]);
    }
}

// ---------------- K3: knn2(64-d) + gather-max over z + b4 -> h2 -------------
// dyn smem (floats):
//   [0, 8320)        sJ buf0: 65 x 128 (row 64 = -|h|^2)
//   [8320, 16640)    sJ buf1
//   [16640, 20736)   sIf: 64 points x 64 floats (h, plain)
//   [20736, 22016)   sTop 64x20 (int)
//   [22016, 22020)   mbar[2] (u64 x2)
#define K3_TILE_BYTES (65 * 128 * 4)
#define K3_SMEM (22024 * 4)
__global__ __launch_bounds__(256, 2) void k3_knn2(const float* __restrict__ b4)
{
    extern __shared__ float sm3[];
    float* sJ0  = sm3;
    float* sJ1  = sm3 + 8320;
    float* sIf  = sm3 + 16640;
    int*   sTop = (int*)(sm3 + 20736);

    int t = threadIdx.x;
    int lane = t & 31;
    int w = t >> 5;
    int b = blockIdx.y;
    int i0 = blockIdx.x * TI;

    u32 sbase = (u32)__cvta_generic_to_shared(sm3);
    u32 mb0 = sbase + 22016 * 4;
    u32 mb1 = mb0 + 8;
    const float* src_base = d_hT2 + (size_t)b * 32 * 8320;

    // fill sIf: 64 points x 64 dims (plain float4 copy)
    {
        const float4* src = (const float4*)d_h;
        for (int idx = t; idx < 64 * 16; idx += 256) {
            int r = idx >> 4, c4 = idx & 15;
            *(float4*)&sIf[r * 64 + c4 * 4] = src[((size_t)b * NN + i0 + r) * 16 + c4];
        }
    }
    if (t == 0) { MBAR_INIT(mb0, 1); MBAR_INIT(mb1, 1); }
    __syncthreads();
    if (t == 0) {
        MBAR_EXPECT_TX(mb0, K3_TILE_BYTES);
        BULK_G2S(sbase, src_base, K3_TILE_BYTES, mb0);
    }

    u64 lst[8];
#pragma unroll
    for (int p = 0; p < 8; p++) lst[p] = (lane < KNB) ? SENT_LO : ~0ull;

    const u64 TWO2 = pack2(2.f, 2.f);

    for (int tt = 0; tt < 32; tt++) {
        __syncthreads();                      // everyone done with buf[(tt+1)&1]
        if (t == 0 && tt + 1 < 32) {
            u32 mbn = ((tt + 1) & 1) ? mb1 : mb0;
            u32 dstn = sbase + (((tt + 1) & 1) ? 8320 * 4 : 0);
            MBAR_EXPECT_TX(mbn, K3_TILE_BYTES);
            BULK_G2S(dstn, src_base + (size_t)(tt + 1) * 8320, K3_TILE_BYTES, mbn);
        }
        u32 mbc = (tt & 1) ? mb1 : mb0;
        MBAR_WAIT(mbc, (tt >> 1) & 1);
        const float* buf = (tt & 1) ? sJ1 : sJ0;
        int j0 = tt * TJ;

        u64 acc[8][2];
#pragma unroll
        for (int p = 0; p < 8; p++) { acc[p][0] = 0ull; acc[p][1] = 0ull; }

#pragma unroll 2
        for (int d4 = 0; d4 < 16; d4++) {
            ulonglong2 bb[4];
#pragma unroll
            for (int dd = 0; dd < 4; dd++)
                bb[dd] = *(const ulonglong2*)&buf[(d4 * 4 + dd) * 128 + lane * 4];
#pragma unroll
            for (int p = 0; p < 8; p++) {
                float4 af = *(const float4*)&sIf[(w * 8 + p) * 64 + d4 * 4];
                u64 a0 = pack2(af.x, af.x);
                u64 a1 = pack2(af.y, af.y);
                u64 a2 = pack2(af.z, af.z);
                u64 a3 = pack2(af.w, af.w);
                acc[p][0] = ffma2(a0, bb[0].x, acc[p][0]);
                acc[p][1] = ffma2(a0, bb[0].y, acc[p][1]);
                acc[p][0] = ffma2(a1, bb[1].x, acc[p][0]);
                acc[p][1] = ffma2(a1, bb[1].y, acc[p][1]);
                acc[p][0] = ffma2(a2, bb[2].x, acc[p][0]);
                acc[p][1] = ffma2(a2, bb[2].y, acc[p][1]);
                acc[p][0] = ffma2(a3, bb[3].x, acc[p][0]);
                acc[p][1] = ffma2(a3, bb[3].y, acc[p][1]);
            }
        }

        ulonglong2 nq = *(const ulonglong2*)&buf[64 * 128 + lane * 4];
#pragma unroll
        for (int p = 0; p < 8; p++) {
            u64 pd0 = ffma2(acc[p][0], TWO2, nq.x);
            u64 pd1 = ffma2(acc[p][1], TWO2, nq.y);
            float pf[4];
            unpack2(pd0, pf[0], pf[1]); unpack2(pd1, pf[2], pf[3]);

            u64 cur = lst[p];
            float thrF = unsort32((u32)(__shfl_sync(FULLM, cur, 0) >> 32));
#pragma unroll
            for (int s = 0; s < 4; s++) {
                u32 ball = __ballot_sync(FULLM, pf[s] >= thrF);
                while (ball) {
                    int src = __ffs(ball) - 1;
                    ball &= ball - 1;
                    float cp = __shfl_sync(FULLM, pf[s], src);
                    sel_insert(cur, sort32(cp), j0 + src * 4 + s);
                }
                thrF = unsort32((u32)(__shfl_sync(FULLM, cur, 0) >> 32));
            }
            lst[p] = cur;
        }
    }

#pragma unroll
    for (int p = 0; p < 8; p++)
        if (lane < KNB)
            sTop[(w * 8 + p) * KNB + lane] = 4095 - (int)(lst[p] & 0xFFFu);
    __syncthreads();

    // gather-max over z: i = t>>2 (64 points), part = t&3 (32 channels each)
    int i = t >> 2, part = t & 3;
    float m[32];
#pragma unroll
    for (int c = 0; c < 32; c++) m[c] = NEG_INF;
    for (int k = 0; k < KNB; k++) {
        const float* zr = d_z + sTop[i * KNB + k] * 128 + part * 32;
#pragma unroll
        for (int c = 0; c < 32; c += 4) {
            float4 zv = *(const float4*)(zr + c);
            m[c]     = fmaxf(m[c],     zv.x);
            m[c + 1] = fmaxf(m[c + 1], zv.y);
            m[c + 2] = fmaxf(m[c + 2], zv.z);
            m[c + 3] = fmaxf(m[c + 3], zv.w);
        }
    }
    int gi = i0 + i;
    float* orow = d_h2 + ((size_t)b * NN + gi) * 128 + part * 32;
    const float* b4p = b4 + part * 32;
#pragma unroll
    for (int c = 0; c < 32; c += 4) {
        *(float4*)(orow + c) = make_float4(m[c] + b4p[c], m[c + 1] + b4p[c + 1],
                                           m[c + 2] + b4p[c + 2], m[c + 3] + b4p[c + 3]);
    }
}

// ---------------- K4: out = h2 @ w5 + b5  (32768x1024, K=128) ---------------
// 128 threads, 8x8 per-thread tile (1.0 B/MAC LDS).
// dyn smem (floats): sA 64x132 [0,8448), sB 128x128 [8448,24832), bias [24832,24960)
#define K4_SMEM (24960 * 4)
__global__ __launch_bounds__(128, 2) void k4_out(
    const float* __restrict__ w5, const float* __restrict__ b5, float* __restrict__ out)
{
    extern __shared__ float sm4[];
    float* sA    = sm4;
    float* sB    = sm4 + 8448;
    float* sBias = sm4 + 24832;

    int t = threadIdx.x;
    int m0 = blockIdx.x * 64;
    int c0 = blockIdx.y * 128;

    {
        const float4* src = (const float4*)d_h2;
        for (int idx = t; idx < 64 * 32; idx += 128) {
            int r = idx >> 5, c4 = idx & 31;
            *(float4*)&sA[r * 132 + c4 * 4] = src[((size_t)m0 + r) * 32 + c4];
        }
    }
    for (int idx = t; idx < 128 * 32; idx += 128) {
        int d = idx >> 5, c4 = idx & 31;
        *(float4*)&sB[d * 128 + c4 * 4] = *(const float4*)&w5[(size_t)d * 1024 + c0 + c4 * 4];
    }
    sBias[t] = b5[c0 + t];
    __syncthreads();

    int tx = t & 15, ty = t >> 4;          // ty 0..7 -> rows ty*8..ty*8+7
    u64 acc[8][4];
#pragma unroll
    for (int ii = 0; ii < 8; ii++)
#pragma unroll
        for (int pp = 0; pp < 4; pp++) acc[ii][pp] = 0ull;

#pragma unroll 2
    for (int d4 = 0; d4 < 32; d4++) {
        float af[8][4];
#pragma unroll
        for (int ii = 0; ii < 8; ii++)
            *(float4*)af[ii] = *(float4*)&sA[(ty * 8 + ii) * 132 + d4 * 4];
#pragma unroll
        for (int dd = 0; dd < 4; dd++) {
            const ulonglong2* bp = (const ulonglong2*)&sB[(d4 * 4 + dd) * 128 + tx * 8];
            ulonglong2 b0 = bp[0];
            ulonglong2 b1 = bp[1];
#pragma unroll
            for (int ii = 0; ii < 8; ii++) {
                u64 a2 = pack2(af[ii][dd], af[ii][dd]);
                acc[ii][0] = ffma2(a2, b0.x, acc[ii][0]);
                acc[ii][1] = ffma2(a2, b0.y, acc[ii][1]);
                acc[ii][2] = ffma2(a2, b1.x, acc[ii][2]);
                acc[ii][3] = ffma2(a2, b1.y, acc[ii][3]);
            }
        }
    }

    const ulonglong2* bi = (const ulonglong2*)&sBias[tx * 8];
    ulonglong2 bv0 = bi[0], bv1 = bi[1];
    const u64 ONE2 = pack2(1.f, 1.f);
#pragma unroll
    for (int ii = 0; ii < 8; ii++) {
        ulonglong2 r0, r1;
        r0.x = ffma2(acc[ii][0], ONE2, bv0.x);
        r0.y = ffma2(acc[ii][1], ONE2, bv0.y);
        r1.x = ffma2(acc[ii][2], ONE2, bv1.x);
        r1.y = ffma2(acc[ii][3], ONE2, bv1.y);
        size_t row = (size_t)(m0 + ty * 8 + ii) * 1024 + c0 + tx * 8;
        *(ulonglong2*)&out[row]     = r0;
        *(ulonglong2*)&out[row + 4] = r1;
    }
}

// ---------------- launch -----------------------------------------------------
extern "C" void kernel_launch(void* const* d_in, const int* in_sizes, int n_in,
                              void* d_out, int out_size)
{
    const float* x  = (const float*)d_in[0];
    const float* w1 = (const float*)d_in[1];
    const float* b1 = (const float*)d_in[2];
    const float* w2 = (const float*)d_in[3];
    const float* b2 = (const float*)d_in[4];
    const float* w3 = (const float*)d_in[5];
    const float* b3 = (const float*)d_in[6];
    const float* w4 = (const float*)d_in[7];
    const float* b4 = (const float*)d_in[8];
    const float* w5 = (const float*)d_in[9];
    const float* b5 = (const float*)d_in[10];
    float* out = (float*)d_out;

    cudaFuncSetAttribute(k1_knn1, cudaFuncAttributeMaxDynamicSharedMemorySize, K1_SMEM);
    cudaFuncSetAttribute(k3_knn2, cudaFuncAttributeMaxDynamicSharedMemorySize, K3_SMEM);
    cudaFuncSetAttribute(k4_out,  cudaFuncAttributeMaxDynamicSharedMemorySize, K4_SMEM);

    k0_mlp_g<<<NN / 8, 256>>>(x, w1, b1, w2, b2, w3, b3);
    k1_knn1<<<dim3(NN / TI, BB), 256, K1_SMEM>>>(x);
    k2_z<<<NN / 64, 256>>>(w4);
    k3_knn2<<<dim3(NN / TI, BB), 256, K3_SMEM>>>(b4);
    k4_out<<<dim3((BB * NN) / 64, 1024 / 128), 128, K4_SMEM>>>(w5, b5, out);
}